// round 13
// baseline (speedup 1.0000x reference)
#include <cuda_runtime.h>
#include <math.h>

// ---------------------------------------------------------------------------
// Problem constants
// ---------------------------------------------------------------------------
namespace {
constexpr int B_   = 2;
constexpr int NV   = 512;
constexpr int FD   = 1024;
constexpr int NH   = 4;
constexpr int DHD  = 256;
constexpr int AHD  = 256;
constexpr int HIDD = 512;
constexpr int OD   = 128;
constexpr int NC   = 10;
constexpr int NSQ  = NV * NV;          // 262144
constexpr int RANK_ = NSQ - 209715;    // 52429 : ascending order statistic index
constexpr float INV_TEMP = 2.0f;       // 1/0.5

// Scratch layout (floats)
constexpr long O_HP  = 0;
constexpr long O_SI  = O_HP  + (long)B_ * NV * FD;       // s_i  [B*NH*NV]
constexpr long O_SJ  = O_SI  + (long)B_ * NH * NV;
constexpr long O_AL  = O_SJ  + (long)B_ * NH * NV;       // alpha [B*NH*NV*NV]
constexpr long O_NF  = O_AL  + (long)B_ * NH * NV * NV;  // node feats
constexpr long O_PI  = O_NF  + (long)B_ * NV * FD;
constexpr long O_PJ  = O_PI  + (long)B_ * NV * AHD;      // must follow PI contiguously
constexpr long O_ED  = O_PJ  + (long)B_ * NV * AHD;      // edge scores
constexpr long O_EX  = O_ED  + (long)B_ * NSQ;           // exp values
constexpr long O_AD  = O_EX  + (long)B_ * NSQ;           // causal adj
constexpr long O_H1  = O_AD  + (long)B_ * NSQ;
constexpr long O_H2  = O_H1  + (long)B_ * NV * FD;
constexpr long O_H3  = O_H2  + (long)B_ * NV * HIDD;
constexpr long O_H4  = O_H3  + (long)B_ * NV * HIDD;
constexpr long O_MAXB = O_H4 + (long)B_ * NV * OD;       // unsigned[B]
constexpr long O_Z    = O_MAXB + B_;
constexpr long O_SK   = O_Z    + B_;
constexpr long O_THR  = O_SK   + B_;
constexpr long O_PFX  = O_THR  + B_;                     // unsigned[B]
constexpr long O_RNK  = O_PFX  + B_;                     // int[B]
constexpr long O_HIST = O_RNK  + B_;                     // int[B*4*256]
constexpr long O_PART = O_HIST + (long)B_ * 4 * 256;     // split-K partials
constexpr long PART_SZ = 8388608;                        // max S*Csize over launches
constexpr long TOTAL  = O_PART + PART_SZ;
} // namespace

__device__ float g_s[TOTAL];

// ---------------------------------------------------------------------------
// Helpers
// ---------------------------------------------------------------------------
__device__ __forceinline__ float warpMax(float v) {
    #pragma unroll
    for (int o = 16; o > 0; o >>= 1) v = fmaxf(v, __shfl_xor_sync(0xffffffffu, v, o));
    return v;
}
__device__ __forceinline__ float warpSum(float v) {
    #pragma unroll
    for (int o = 16; o > 0; o >>= 1) v += __shfl_xor_sync(0xffffffffu, v, o);
    return v;
}
__device__ __forceinline__ unsigned fenc(float f) {
    unsigned u = __float_as_uint(f);
    return (u & 0x80000000u) ? ~u : (u | 0x80000000u);
}
__device__ __forceinline__ float fdec(unsigned u) {
    u = (u & 0x80000000u) ? (u & 0x7fffffffu) : ~u;
    return __uint_as_float(u);
}
// round-to-nearest tf32 (result is fp32 bits with low mantissa zeroed)
__device__ __forceinline__ float t32(float x) {
    unsigned u;
    asm("cvt.rna.tf32.f32 %0, %1;" : "=r"(u) : "f"(x));
    return __uint_as_float(u);
}
__device__ __forceinline__ void mma_tf32(float c[4], const float a[4], const float b[2]) {
    asm volatile(
        "mma.sync.aligned.m16n8k8.row.col.f32.tf32.tf32.f32 "
        "{%0,%1,%2,%3}, {%4,%5,%6,%7}, {%8,%9}, {%0,%1,%2,%3};"
        : "+f"(c[0]), "+f"(c[1]), "+f"(c[2]), "+f"(c[3])
        : "r"(__float_as_uint(a[0])), "r"(__float_as_uint(a[1])),
          "r"(__float_as_uint(a[2])), "r"(__float_as_uint(a[3])),
          "r"(__float_as_uint(b[0])), "r"(__float_as_uint(b[1])));
}

// ---------------------------------------------------------------------------
// tf32 tensor-core GEMM, v4: block 128(M) x 128(N) x 16(K), warp tile 32x64.
//   MODE 0: C = A * B^T   (B row-major N x K)
//   MODE 1: C = A * B     (B row-major K x N)
// 256 threads = 8 warps (4 M-rows x 2 N-cols); each warp: 2x8 m16n8k8 MMAs.
// Fragment-packed smem (one LDS.128 per a-frag, one LDS.64 per b-frag),
// double-buffered stages, 1-deep register prefetch, split-K.
//
// Packed A (per stage, 2048 floats): idx = (Rb*2+kb)*128 + (tig*8+g)*4 + slot
//   slot -> { A[Rb*16+g][kb*8+tig], A[Rb*16+8+g][kb*8+tig],
//             A[Rb*16+g][kb*8+tig+4], A[Rb*16+8+g][kb*8+tig+4] }
// Packed B (per stage, 2048 floats): idx = (Nb*2+kb)*64 + (tig*8+(g^(Nb&7)))*2
//   + shi; float2 = { B[Nb*8+g][kb*8+tig], B[Nb*8+g][kb*8+tig+4] }, Nb 0..15.
//
// Split-K: gridDim.z = NB * S; s = z / NB, partial C at s*sStride.
// Batch zb = z % NB: offset = (zb/zdiv)*S1 + (zb%zdiv)*S2.
// M % 128 == 0, N % 128 == 0, K % 16 == 0, K >= 16.
// ---------------------------------------------------------------------------
template <int MODE>
__global__ void __launch_bounds__(256, 2) mma_gemm_k(
    const float* __restrict__ A, const float* __restrict__ Bm,
    float* __restrict__ C,
    int K, int lda, int ldb, int ldc, int zdiv, int S,
    long aS1, long aS2, long bS1, long bS2, long cS1, long cS2,
    long sStride)
{
    __shared__ float sA[2][2048];   // 8KB per stage
    __shared__ float sB[2][2048];   // 8KB per stage

    int NB = gridDim.z / S;
    int s  = blockIdx.z / NB;
    int zb = blockIdx.z % NB;
    int z1 = zb / zdiv, z2 = zb - z1 * zdiv;
    A  += z1 * aS1 + z2 * aS2;
    Bm += z1 * bS1 + z2 * bS2;
    C  += z1 * cS1 + z2 * cS2;
    // split-K offsets
    A += (long)s * K;                       // A is [M, K_total] row-major
    if (MODE == 0) Bm += (long)s * K;       // B is [N, K_total]
    else           Bm += (long)s * K * ldb; // B is [K_total, N]
    C += (long)s * sStride;

    int m0 = blockIdx.y * 128;
    int n0 = blockIdx.x * 128;
    int tid  = threadIdx.x;
    int lane = tid & 31;
    int wid  = tid >> 5;
    int g   = lane >> 2, tig = lane & 3;
    int wm = (wid >> 1) * 32;        // 0,32,64,96
    int wn = (wid & 1) * 64;         // 0,64

    // ---- A loader: rows {arow, arow+64}, cols [acol, acol+4) ----
    int arow = tid >> 2;
    int acol = (tid & 3) * 4;
    const float* Ap0 = A + (long)(m0 + arow) * lda + acol;
    const float* Ap1 = Ap0 + (long)64 * lda;
    int kb_a  = acol >> 3;
    int shi_a = (acol >> 2) & 1;
    int aBase0, aBase1;
    {
        int m_l = arow;
        aBase0 = ((m_l >> 4) * 2 + kb_a) * 128 + (m_l & 7) * 4 + shi_a * 2 + ((m_l >> 3) & 1);
        m_l = arow + 64;
        aBase1 = ((m_l >> 4) * 2 + kb_a) * 128 + (m_l & 7) * 4 + shi_a * 2 + ((m_l >> 3) & 1);
    }

    // ---- B loader: two float4 per thread; second set at Nb+8 (+1024) ----
    const float* Bp0;
    const float* Bp1;
    int bAddr[4];
    if (MODE == 0) {
        int brow = tid >> 2;            // n_local 0..63 (and +64)
        int bcol = (tid & 3) * 4;       // k offset
        Bp0 = Bm + (long)(n0 + brow) * ldb + bcol;
        Bp1 = Bp0 + (long)64 * ldb;
        int Nb = brow >> 3, gB = brow & 7;
        int gx = gB ^ (Nb & 7);
        int kb_b = bcol >> 3, shi_b = (bcol >> 2) & 1;
        #pragma unroll
        for (int t = 0; t < 4; t++)
            bAddr[t] = (Nb * 2 + kb_b) * 64 + (t * 8 + gx) * 2 + shi_b;
    } else {
        int krow = tid >> 4;            // k_local (0..15)
        int bn   = (tid & 15) * 4;      // n offset 0..60 (and +64)
        Bp0 = Bm + (long)krow * ldb + n0 + bn;
        Bp1 = Bp0 + 64;
        int kb_b = krow >> 3, tig_b = krow & 3, shi_b = (krow >> 2) & 1;
        #pragma unroll
        for (int t = 0; t < 4; t++) {
            int n_l = bn + t;
            int Nb = n_l >> 3, gB = n_l & 7;
            int gx = gB ^ (Nb & 7);
            bAddr[t] = (Nb * 2 + kb_b) * 64 + (tig_b * 8 + gx) * 2 + shi_b;
        }
    }

    // ---- consumer fragment addresses ----
    int aIdx0 = ((wm >> 4) * 2) * 128 + (tig * 8 + g) * 4;
    int aIdx1 = ((wm >> 4) * 2 + 2) * 128 + (tig * 8 + g) * 4;
    int bIdx[8];
    #pragma unroll
    for (int nt = 0; nt < 8; nt++) {
        int Nb = (wn >> 3) + nt;
        bIdx[nt] = (Nb * 2) * 64 + (tig * 8 + (g ^ (Nb & 7))) * 2;
    }

    float c[2][8][4] = {};

    float4 ra0, ra1, rb0, rb1;

    auto sts = [&](int st) {
        float* SA = sA[st];
        float* SB = sB[st];
        const float* v0 = (const float*)&ra0;
        const float* v1 = (const float*)&ra1;
        const float* w0 = (const float*)&rb0;
        const float* w1 = (const float*)&rb1;
        #pragma unroll
        for (int t = 0; t < 4; t++) {
            SA[aBase0 + t * 32]   = t32(v0[t]);
            SA[aBase1 + t * 32]   = t32(v1[t]);
            SB[bAddr[t]]          = t32(w0[t]);
            SB[bAddr[t] + 1024]   = t32(w1[t]);
        }
    };

    auto compute = [&](int p) {
        const float* SA = sA[p];
        const float* SB = sB[p];
        #pragma unroll
        for (int kb = 0; kb < 2; kb++) {
            float4 av0 = *(const float4*)(SA + aIdx0 + kb * 128);
            float4 av1 = *(const float4*)(SA + aIdx1 + kb * 128);
            float a0[4] = {av0.x, av0.y, av0.z, av0.w};
            float a1[4] = {av1.x, av1.y, av1.z, av1.w};
            #pragma unroll
            for (int nt = 0; nt < 8; nt++) {
                float2 bv = *(const float2*)(SB + bIdx[nt] + kb * 64);
                float bb[2] = {bv.x, bv.y};
                mma_tf32(c[0][nt], a0, bb);
                mma_tf32(c[1][nt], a1, bb);
            }
        }
    };

    // prologue
    ra0 = *(const float4*)Ap0;
    ra1 = *(const float4*)Ap1;
    rb0 = *(const float4*)Bp0;
    rb1 = *(const float4*)Bp1;
    sts(0);
    __syncthreads();

    int p = 0;
    for (int k0 = 16; k0 < K; k0 += 16) {
        Ap0 += 16; Ap1 += 16;
        if (MODE == 0) { Bp0 += 16; Bp1 += 16; }
        else           { Bp0 += (long)16 * ldb; Bp1 += (long)16 * ldb; }
        ra0 = *(const float4*)Ap0;      // LDG for next tile (overlaps compute)
        ra1 = *(const float4*)Ap1;
        rb0 = *(const float4*)Bp0;
        rb1 = *(const float4*)Bp1;
        compute(p);
        sts(p ^ 1);
        __syncthreads();
        p ^= 1;
    }
    compute(p);

    // epilogue (no bias — applied by the split-K reducer)
    #pragma unroll
    for (int mt = 0; mt < 2; mt++) {
        #pragma unroll
        for (int nt = 0; nt < 8; nt++) {
            int m = m0 + wm + mt * 16 + g;
            int n = n0 + wn + nt * 8 + 2 * tig;
            *(float2*)&C[(long)m * ldc + n] =
                make_float2(c[mt][nt][0], c[mt][nt][1]);
            *(float2*)&C[(long)(m + 8) * ldc + n] =
                make_float2(c[mt][nt][2], c[mt][nt][3]);
        }
    }
}

// ---------------------------------------------------------------------------
// Split-K reducer: out[i] = sum_s part[i + s*sStride] (+ bias[col]).
// All counts in float4 units; ldc % 4 == 0.
// ---------------------------------------------------------------------------
__global__ void __launch_bounds__(256) reduce_k(
    const float* __restrict__ part, float* __restrict__ outp,
    const float* __restrict__ bias, int ldc,
    long n4, int S, long sStride4)
{
    const float4* p4 = reinterpret_cast<const float4*>(part);
    float4* o4 = reinterpret_cast<float4*>(outp);
    for (long i = blockIdx.x * 256 + threadIdx.x; i < n4;
         i += (long)gridDim.x * 256) {
        float4 a = p4[i];
        for (int s = 1; s < S; s++) {
            float4 b = p4[i + s * sStride4];
            a.x += b.x; a.y += b.y; a.z += b.z; a.w += b.w;
        }
        if (bias) {
            int col = (int)((i * 4) % ldc);
            a.x += bias[col]; a.y += bias[col + 1];
            a.z += bias[col + 2]; a.w += bias[col + 3];
        }
        o4[i] = a;
    }
}

// ---------------------------------------------------------------------------
// Attention scores: s_i/s_j per (b,h,n) — one warp per row.
// ---------------------------------------------------------------------------
__global__ void attn_scores_k(const float* __restrict__ hp,
                              const float* __restrict__ attn,
                              float* __restrict__ si, float* __restrict__ sj)
{
    int w = (blockIdx.x * blockDim.x + threadIdx.x) >> 5;
    int lane = threadIdx.x & 31;
    if (w >= B_ * NH * NV) return;
    int b = w / (NH * NV);
    int rem = w - b * NH * NV;
    int h = rem / NV;
    int n = rem - h * NV;

    const float* v  = hp + ((long)(b * NV + n)) * FD + h * DHD;
    const float* ai = attn + h * 2 * DHD;
    const float* aj = ai + DHD;
    float s1 = 0.f, s2 = 0.f;
    #pragma unroll 4
    for (int d = lane; d < DHD; d += 32) {
        float x = v[d];
        s1 = fmaf(x, ai[d], s1);
        s2 = fmaf(x, aj[d], s2);
    }
    s1 = warpSum(s1);
    s2 = warpSum(s2);
    if (lane == 0) { si[w] = s1; sj[w] = s2; }
}

// ---------------------------------------------------------------------------
// Attention softmax per (b,h,i) row: alpha = softmax_j(lrelu(s_i + s_j)).
// ---------------------------------------------------------------------------
__global__ void __launch_bounds__(128) attn_softmax_k(
    const float* __restrict__ si, const float* __restrict__ sj,
    float* __restrict__ alpha)
{
    int row = blockIdx.x;                 // [0, B*NH*NV)
    int bh  = row / NV;
    float s_i = si[row];
    const float* sjr = sj + (long)bh * NV;
    __shared__ float red[4];

    int t = threadIdx.x;
    float loc[4];
    float m = -3.4e38f;
    #pragma unroll
    for (int r = 0; r < 4; r++) {
        float e = s_i + sjr[t + 128 * r];
        e = (e >= 0.f) ? e : 0.2f * e;
        loc[r] = e;
        m = fmaxf(m, e);
    }
    m = warpMax(m);
    if ((t & 31) == 0) red[t >> 5] = m;
    __syncthreads();
    float bm = fmaxf(fmaxf(red[0], red[1]), fmaxf(red[2], red[3]));

    float s = 0.f;
    #pragma unroll
    for (int r = 0; r < 4; r++) {
        float ex = expf(loc[r] - bm);
        loc[r] = ex;
        s += ex;
    }
    s = warpSum(s);
    __syncthreads();
    if ((t & 31) == 0) red[t >> 5] = s;
    __syncthreads();
    float inv = 1.0f / (red[0] + red[1] + red[2] + red[3]);
    #pragma unroll
    for (int r = 0; r < 4; r++)
        alpha[(long)row * NV + t + 128 * r] = loc[r] * inv;
}

// ---------------------------------------------------------------------------
// Fused edge scorer + global max (feeds softmax):
// edge[b,i,j] = b2 + sum_a relu(pi[b,i,a]+pj[b,j,a]) * w2[a]
// ---------------------------------------------------------------------------
__global__ void __launch_bounds__(256) edge_k(
    const float* __restrict__ pi, const float* __restrict__ pj,
    const float* __restrict__ w2, const float* __restrict__ b2,
    float* __restrict__ edge, unsigned* __restrict__ maxb)
{
    int b  = blockIdx.z;
    int i0 = blockIdx.y * 32, j0 = blockIdx.x * 32;
    __shared__ float spi[32][33];
    __shared__ float spj[32][33];
    __shared__ float sw2[32];

    const float* PI = pi + (long)b * NV * AHD;
    const float* PJ = pj + (long)b * NV * AHD;
    int tid = threadIdx.x;
    int tx = tid & 31, ty = tid >> 5;   // ty 0..7
    float acc[4] = {0.f, 0.f, 0.f, 0.f};

    for (int a0 = 0; a0 < AHD; a0 += 32) {
        #pragma unroll
        for (int r = 0; r < 4; r++) {
            spi[ty + 8 * r][tx] = PI[(long)(i0 + ty + 8 * r) * AHD + a0 + tx];
            spj[ty + 8 * r][tx] = PJ[(long)(j0 + ty + 8 * r) * AHD + a0 + tx];
        }
        if (tid < 32) sw2[tid] = w2[a0 + tid];
        __syncthreads();

        #pragma unroll
        for (int a = 0; a < 32; a++) {
            float pjv = spj[tx][a];
            float wv  = sw2[a];
            #pragma unroll
            for (int r = 0; r < 4; r++) {
                float v = spi[ty + 8 * r][a] + pjv;
                acc[r] = fmaf(fmaxf(v, 0.f), wv, acc[r]);
            }
        }
        __syncthreads();
    }
    float bb = b2[0];
    float lm = -3.4e38f;
    #pragma unroll
    for (int r = 0; r < 4; r++) {
        float v = acc[r] + bb;
        edge[((long)b * NV + i0 + ty + 8 * r) * NV + j0 + tx] = v;
        lm = fmaxf(lm, v);
    }
    lm = warpMax(lm);
    __shared__ float red[8];
    if (tx == 0) red[ty] = lm;
    __syncthreads();
    if (tid == 0) {
        float bm = red[0];
        #pragma unroll
        for (int i = 1; i < 8; i++) bm = fmaxf(bm, red[i]);
        atomicMax(maxb + b, fenc(bm));
    }
}

// ---------------------------------------------------------------------------
// Softmax + top-k selection pipeline over the flat (B, N*N) edge scores.
// ---------------------------------------------------------------------------
__global__ void init_k(unsigned* maxb, float* Z, float* sk,
                       unsigned* pfx, int* rnk, int* hist)
{
    int t = blockIdx.x * blockDim.x + threadIdx.x;
    if (t < B_) { maxb[t] = 0u; Z[t] = 0.f; sk[t] = 0.f; pfx[t] = 0u; rnk[t] = RANK_; }
    for (int i = t; i < B_ * 4 * 256; i += gridDim.x * blockDim.x) hist[i] = 0;
}

// exp + Z sum + radix pass-0 histogram (top byte), fused.
__global__ void __launch_bounds__(256) exp_k(const float* __restrict__ edge,
                                             const unsigned* __restrict__ maxb,
                                             float* __restrict__ expb,
                                             float* __restrict__ Z,
                                             int* __restrict__ hist)
{
    int b = blockIdx.y;
    float emax = fdec(maxb[b]);
    const float* e = edge + (long)b * NSQ;
    float* o = expb + (long)b * NSQ;
    __shared__ int sh[256];
    sh[threadIdx.x] = 0;
    __syncthreads();
    float s = 0.f;
    for (int i = blockIdx.x * 256 + threadIdx.x; i < NSQ; i += 64 * 256) {
        float ex = expf((e[i] - emax) * INV_TEMP);
        o[i] = ex;
        s += ex;
        atomicAdd(&sh[__float_as_uint(ex) >> 24], 1);
    }
    s = warpSum(s);
    __shared__ float red[8];
    if ((threadIdx.x & 31) == 0) red[threadIdx.x >> 5] = s;
    __syncthreads();
    if (threadIdx.x == 0) {
        float t = 0.f;
        #pragma unroll
        for (int i = 0; i < 8; i++) t += red[i];
        atomicAdd(Z + b, t);
    }
    int c = sh[threadIdx.x];
    if (c) atomicAdd(&hist[(long)b * 4 * 256 + threadIdx.x], c);
}

// Byte-radix histogram over positive-float bit patterns (passes 1..3).
__global__ void __launch_bounds__(256) hist_k(const float* __restrict__ expb,
                                              const unsigned* __restrict__ pfx_,
                                              int* __restrict__ hist, int pass)
{
    int b = blockIdx.y;
    const unsigned* u = reinterpret_cast<const unsigned*>(expb + (long)b * NSQ);
    unsigned pfx = pfx_[b];
    int shift = 24 - 8 * pass;
    __shared__ int sh[256];
    sh[threadIdx.x] = 0;
    __syncthreads();
    for (int i = blockIdx.x * 256 + threadIdx.x; i < NSQ; i += 64 * 256) {
        unsigned v = u[i];
        if ((v >> (shift + 8)) == pfx)
            atomicAdd(&sh[(v >> shift) & 255], 1);
    }
    __syncthreads();
    int c = sh[threadIdx.x];
    if (c) atomicAdd(&hist[((long)b * 4 + pass) * 256 + threadIdx.x], c);
}

__global__ void decide_k(const int* __restrict__ hist, unsigned* pfx, int* rnk,
                         float* thr, int pass)
{
    if (threadIdx.x != 0) return;
    int b = blockIdx.x;
    const int* H = hist + ((long)b * 4 + pass) * 256;
    int rk = rnk[b];
    unsigned p = pfx[b];
    int cum = 0, bkt = 255;
    for (int t = 0; t < 256; t++) {
        int c = H[t];
        if (cum + c > rk) { bkt = t; break; }
        cum += c;
    }
    p = (p << 8) | (unsigned)bkt;
    pfx[b] = p;
    rnk[b] = rk - cum;
    if (pass == 3) thr[b] = __uint_as_float(p);
}

__global__ void __launch_bounds__(256) skept_k(const float* __restrict__ expb,
                                               const float* __restrict__ thr,
                                               float* __restrict__ sk)
{
    int b = blockIdx.y;
    float t = thr[b];
    const float* e = expb + (long)b * NSQ;
    float s = 0.f;
    for (int i = blockIdx.x * 256 + threadIdx.x; i < NSQ; i += 64 * 256) {
        float v = e[i];
        if (v >= t) s += v;
    }
    s = warpSum(s);
    __shared__ float red[8];
    if ((threadIdx.x & 31) == 0) red[threadIdx.x >> 5] = s;
    __syncthreads();
    if (threadIdx.x == 0) {
        float bs = 0.f;
        #pragma unroll
        for (int i = 0; i < 8; i++) bs += red[i];
        atomicAdd(sk + b, bs);
    }
}

__global__ void __launch_bounds__(256) adj_k(const float* __restrict__ expb,
                                             const float* __restrict__ thr,
                                             const float* __restrict__ sk,
                                             const float* __restrict__ Z,
                                             float* __restrict__ adj)
{
    int b = blockIdx.y;
    float t = thr[b];
    float inv = 1.0f / (sk[b] + 1e-12f * Z[b]);
    const float* e = expb + (long)b * NSQ;
    float* o = adj + (long)b * NSQ;
    for (int i = blockIdx.x * 256 + threadIdx.x; i < NSQ; i += 64 * 256) {
        float v = e[i];
        o[i] = (v >= t) ? v * inv : 0.f;
    }
}

// ---------------------------------------------------------------------------
// Fused batchnorm (+relu), stats over all R = B*N rows jointly.
// ---------------------------------------------------------------------------
__global__ void __launch_bounds__(256) bn_relu_k(float* __restrict__ h,
                                                 const float* __restrict__ gam,
                                                 const float* __restrict__ bet,
                                                 int R, int C)
{
    int l = threadIdx.x & 63;
    int part = threadIdx.x >> 6;
    int c = blockIdx.x * 64 + l;
    float s = 0.f, s2 = 0.f;
    for (int r = part; r < R; r += 4) {
        float v = h[(long)r * C + c];
        s += v;
        s2 = fmaf(v, v, s2);
    }
    __shared__ float sh1[4][64], sh2[4][64], sm[64], sv[64];
    sh1[part][l] = s;
    sh2[part][l] = s2;
    __syncthreads();
    if (part == 0) {
        float t1 = sh1[0][l] + sh1[1][l] + sh1[2][l] + sh1[3][l];
        float t2 = sh2[0][l] + sh2[1][l] + sh2[2][l] + sh2[3][l];
        float mean = t1 / (float)R;
        float var  = t2 / (float)R - mean * mean;
        sm[l] = mean;
        sv[l] = rsqrtf(var + 1e-5f);
    }
    __syncthreads();
    float scale = sv[l] * gam[c];
    float shift = bet[c] - sm[l] * scale;
    for (int r = part; r < R; r += 4) {
        long idx = (long)r * C + c;
        h[idx] = fmaxf(fmaf(h[idx], scale, shift), 0.f);
    }
}

// ---------------------------------------------------------------------------
// Final: feat = mean_n h4[b,n,:]; out = feat @ cls_w^T + cls_b
// ---------------------------------------------------------------------------
__global__ void __launch_bounds__(128) final_k(const float* __restrict__ h4,
                                               const float* __restrict__ cw,
                                               const float* __restrict__ cb,
                                               float* __restrict__ out)
{
    int b = blockIdx.x;
    int c = threadIdx.x;   // 128 = OD
    __shared__ float sf[OD];
    float s = 0.f;
    for (int n = 0; n < NV; n++)
        s += h4[((long)b * NV + n) * OD + c];
    sf[c] = s * (1.0f / (float)NV);
    __syncthreads();
    if (c < NC) {
        float d = cb[c];
        for (int f = 0; f < OD; f++)
            d = fmaf(sf[f], cw[c * OD + f], d);
        out[b * NC + c] = d;
    }
}

// ---------------------------------------------------------------------------
// Launcher
// ---------------------------------------------------------------------------
extern "C" void kernel_launch(void* const* d_in, const int* in_sizes, int n_in,
                              void* d_out, int out_size)
{
    const float* x    = (const float*)d_in[0];
    const float* Wg   = (const float*)d_in[1];
    const float* attn = (const float*)d_in[2];
    const float* W1   = (const float*)d_in[3];
    const float* b1   = (const float*)d_in[4];
    const float* w2   = (const float*)d_in[5];
    const float* b2   = (const float*)d_in[6];
    const float* gc1w = (const float*)d_in[7];
    const float* gc1b = (const float*)d_in[8];
    const float* bn1g = (const float*)d_in[9];
    const float* bn1b = (const float*)d_in[10];
    const float* gc2w = (const float*)d_in[11];
    const float* gc2b = (const float*)d_in[12];
    const float* bn2g = (const float*)d_in[13];
    const float* bn2b = (const float*)d_in[14];
    const float* clsw = (const float*)d_in[15];
    const float* clsb = (const float*)d_in[16];
    float* out = (float*)d_out;

    float* sb = nullptr;
    cudaGetSymbolAddress((void**)&sb, g_s);

    float* HP = sb + O_HP;
    float* SI = sb + O_SI;
    float* SJ = sb + O_SJ;
    float* AL = sb + O_AL;
    float* NF = sb + O_NF;
    float* PI = sb + O_PI;
    float* PJ = sb + O_PJ;
    float* ED = sb + O_ED;
    float* EX = sb + O_EX;
    float* AD = sb + O_AD;
    float* H1 = sb + O_H1;
    float* H2 = sb + O_H2;
    float* H3 = sb + O_H3;
    float* H4 = sb + O_H4;
    float* PART = sb + O_PART;
    unsigned* MAXB = reinterpret_cast<unsigned*>(sb + O_MAXB);
    float* Zp  = sb + O_Z;
    float* SK  = sb + O_SK;
    float* THR = sb + O_THR;
    unsigned* PFX = reinterpret_cast<unsigned*>(sb + O_PFX);
    int* RNK = reinterpret_cast<int*>(sb + O_RNK);
    int* HIST = reinterpret_cast<int*>(sb + O_HIST);

    const int RG = 256;   // reduce grid

    // 0. init selection state (MAXB must be ready before edge_k)
    init_k<<<8, 256>>>(MAXB, Zp, SK, PFX, RNK, HIST);

    // 1. hp = x @ Wg^T : M=1024, N=1024, S=4 -> 256 CTAs, K=256/split
    mma_gemm_k<0><<<dim3(FD / 128, (B_ * NV) / 128, 4), 256>>>(
        x, Wg, PART, 256, FD, FD, FD, 1, 4, 0, 0, 0, 0, 0, 0, 1048576);
    reduce_k<<<RG, 256>>>(PART, HP, nullptr, FD, 262144, 4, 262144);

    // 2. s_i, s_j
    attn_scores_k<<<(B_ * NH * NV * 32 + 255) / 256, 256>>>(HP, attn, SI, SJ);

    // 3. alpha = softmax(lrelu(s_i + s_j))
    attn_softmax_k<<<B_ * NH * NV, 128>>>(SI, SJ, AL);

    // 4. node_feats = alpha @ hp_heads  (NB=8 over b,h; S=4 -> 256 CTAs, K=128)
    mma_gemm_k<1><<<dim3(DHD / 128, NV / 128, 8 * 4), 256>>>(
        AL, HP, PART, 128, NV, FD, FD, NH, 4,
        (long)NH * NSQ, (long)NSQ, (long)NV * FD, (long)DHD,
        (long)NV * FD, (long)DHD, 1048576);
    reduce_k<<<RG, 256>>>(PART, NF, nullptr, FD, 262144, 4, 262144);

    // 5+6. pi|pj = nf @ W1{i,j}^T  (NB=2 halves, S=8 -> 256 CTAs, K=128);
    // reducer adds b1 to both halves (b1 is zeros in this problem instance).
    mma_gemm_k<0><<<dim3(AHD / 128, (B_ * NV) / 128, 2 * 8), 256>>>(
        NF, W1, PART, 128, FD, 2 * FD, AHD, 2, 8,
        0, 0, 0, (long)FD, 0, (long)B_ * NV * AHD, 1048576);
    reduce_k<<<RG, 256>>>(PART, PI, b1, AHD, 262144, 8, 262144);

    // 7. edge scores (fused relu-dot with w2) + global max
    edge_k<<<dim3(NV / 32, NV / 32, B_), 256>>>(PI, PJ, w2, b2, ED, MAXB);

    // 8-18. softmax + rank-52429 threshold + masked renormalize
    exp_k<<<dim3(64, B_), 256>>>(ED, MAXB, EX, Zp, HIST);
    decide_k<<<B_, 32>>>(HIST, PFX, RNK, THR, 0);
    for (int pass = 1; pass < 4; pass++) {
        hist_k<<<dim3(64, B_), 256>>>(EX, PFX, HIST, pass);
        decide_k<<<B_, 32>>>(HIST, PFX, RNK, THR, pass);
    }
    skept_k<<<dim3(64, B_), 256>>>(EX, THR, SK);
    adj_k<<<dim3(64, B_), 256>>>(EX, THR, SK, Zp, AD);

    // 19. h1 = adj @ nf   (NB=2 batches, S=4 -> 256 CTAs, K=128)
    mma_gemm_k<1><<<dim3(FD / 128, NV / 128, 2 * 4), 256>>>(
        AD, NF, PART, 128, NV, FD, FD, 1, 4,
        (long)NSQ, 0, (long)NV * FD, 0, (long)NV * FD, 0, 1048576);
    reduce_k<<<RG, 256>>>(PART, H1, nullptr, FD, 262144, 4, 262144);

    // 20. h2 = h1 @ gc1_w^T + gc1_b  (S=8 -> 256 CTAs, K=128)
    mma_gemm_k<0><<<dim3(HIDD / 128, (B_ * NV) / 128, 8), 256>>>(
        H1, gc1w, PART, 128, FD, FD, HIDD, 1, 8, 0, 0, 0, 0, 0, 0, 524288);
    reduce_k<<<RG, 256>>>(PART, H2, gc1b, HIDD, 131072, 8, 131072);

    // 21. bn1 + relu
    bn_relu_k<<<HIDD / 64, 256>>>(H2, bn1g, bn1b, B_ * NV, HIDD);

    // 22. h3 = adj @ h2  (NB=2, S=8 -> 256 CTAs, K=64)
    mma_gemm_k<1><<<dim3(HIDD / 128, NV / 128, 2 * 8), 256>>>(
        AD, H2, PART, 64, NV, HIDD, HIDD, 1, 8,
        (long)NSQ, 0, (long)NV * HIDD, 0, (long)NV * HIDD, 0, 524288);
    reduce_k<<<RG, 256>>>(PART, H3, nullptr, HIDD, 131072, 8, 131072);

    // 23. h4 = h3 @ gc2_w^T + gc2_b  (S=8 -> 64 CTAs, K=64)
    mma_gemm_k<0><<<dim3(OD / 128, (B_ * NV) / 128, 8), 256>>>(
        H3, gc2w, PART, 64, HIDD, HIDD, OD, 1, 8, 0, 0, 0, 0, 0, 0, 131072);
    reduce_k<<<RG, 256>>>(PART, H4, gc2b, OD, 32768, 8, 32768);

    // 24. bn2 + relu
    bn_relu_k<<<OD / 64, 256>>>(H4, bn2g, bn2b, B_ * NV, OD);

    // 25. mean-pool + classifier
    final_k<<<B_, 128>>>(H4, clsw, clsb, out);
}

// round 15
// speedup vs baseline: 1.4344x; 1.4344x over previous
#include <cuda_runtime.h>
#include <math.h>

// ---------------------------------------------------------------------------
// Problem constants
// ---------------------------------------------------------------------------
namespace {
constexpr int B_   = 2;
constexpr int NV   = 512;
constexpr int FD   = 1024;
constexpr int NH   = 4;
constexpr int DHD  = 256;
constexpr int AHD  = 256;
constexpr int HIDD = 512;
constexpr int OD   = 128;
constexpr int NC   = 10;
constexpr int NSQ  = NV * NV;          // 262144
constexpr int RANK_ = NSQ - 209715;    // 52429 : ascending order statistic index
constexpr float INV_TEMP = 2.0f;       // 1/0.5

// Scratch layout (floats)
constexpr long O_HP  = 0;
constexpr long O_SI  = O_HP  + (long)B_ * NV * FD;       // s_i  [B*NH*NV]
constexpr long O_SJ  = O_SI  + (long)B_ * NH * NV;
constexpr long O_AL  = O_SJ  + (long)B_ * NH * NV;       // alpha [B*NH*NV*NV]
constexpr long O_NF  = O_AL  + (long)B_ * NH * NV * NV;  // node feats
constexpr long O_PI  = O_NF  + (long)B_ * NV * FD;
constexpr long O_PJ  = O_PI  + (long)B_ * NV * AHD;      // must follow PI contiguously
constexpr long O_ED  = O_PJ  + (long)B_ * NV * AHD;      // edge scores
constexpr long O_EX  = O_ED  + (long)B_ * NSQ;           // exp values
constexpr long O_AD  = O_EX  + (long)B_ * NSQ;           // (unused; kept for layout)
constexpr long O_H1  = O_AD  + (long)B_ * NSQ;
constexpr long O_H2  = O_H1  + (long)B_ * NV * FD;
constexpr long O_H3  = O_H2  + (long)B_ * NV * HIDD;
constexpr long O_H4  = O_H3  + (long)B_ * NV * HIDD;
constexpr long O_MAXB = O_H4 + (long)B_ * NV * OD;       // unsigned[B]
constexpr long O_Z    = O_MAXB + B_;
constexpr long O_SK   = O_Z    + B_;
constexpr long O_THR  = O_SK   + B_;
constexpr long O_PFX  = O_THR  + B_;                     // unsigned[B]
constexpr long O_RNK  = O_PFX  + B_;                     // int[B]
constexpr long O_HIST = O_RNK  + B_;                     // int[B*4*256]
constexpr long O_PART = O_HIST + (long)B_ * 4 * 256;     // split-K partials
constexpr long PART_SZ = 2097152;                        // max S*Csize over launches
constexpr long TOTAL  = O_PART + PART_SZ;
} // namespace

__device__ float g_s[TOTAL];

// ---------------------------------------------------------------------------
// Helpers
// ---------------------------------------------------------------------------
__device__ __forceinline__ float warpMax(float v) {
    #pragma unroll
    for (int o = 16; o > 0; o >>= 1) v = fmaxf(v, __shfl_xor_sync(0xffffffffu, v, o));
    return v;
}
__device__ __forceinline__ float warpSum(float v) {
    #pragma unroll
    for (int o = 16; o > 0; o >>= 1) v += __shfl_xor_sync(0xffffffffu, v, o);
    return v;
}
__device__ __forceinline__ unsigned fenc(float f) {
    unsigned u = __float_as_uint(f);
    return (u & 0x80000000u) ? ~u : (u | 0x80000000u);
}
__device__ __forceinline__ float fdec(unsigned u) {
    u = (u & 0x80000000u) ? (u & 0x7fffffffu) : ~u;
    return __uint_as_float(u);
}
// round-to-nearest tf32 (result is fp32 bits with low mantissa zeroed)
__device__ __forceinline__ float t32(float x) {
    unsigned u;
    asm("cvt.rna.tf32.f32 %0, %1;" : "=r"(u) : "f"(x));
    return __uint_as_float(u);
}
__device__ __forceinline__ void mma_tf32(float c[4], const float a[4], const float b[2]) {
    asm volatile(
        "mma.sync.aligned.m16n8k8.row.col.f32.tf32.tf32.f32 "
        "{%0,%1,%2,%3}, {%4,%5,%6,%7}, {%8,%9}, {%0,%1,%2,%3};"
        : "+f"(c[0]), "+f"(c[1]), "+f"(c[2]), "+f"(c[3])
        : "r"(__float_as_uint(a[0])), "r"(__float_as_uint(a[1])),
          "r"(__float_as_uint(a[2])), "r"(__float_as_uint(a[3])),
          "r"(__float_as_uint(b[0])), "r"(__float_as_uint(b[1])));
}

// ---------------------------------------------------------------------------
// tf32 tensor-core GEMM (R12 config): fragment-packed smem + double buffering
// + 2-deep global prefetch + split-K.
//   MODE 0: C = A * B^T   (B row-major N x K)
//   MODE 1: C = A * B     (B row-major K x N)
// Block tile 128(M) x 64(N) x 16(K), 256 threads = 8 warps (4x2),
// warp tile 32x32 via 2x4 m16n8k8 tf32 MMAs, fp32 accumulate.
//
// TRANSA == 1 (MODE 1 only): A values are transformed on load as
//   a = (a >= thr[z1]) ? a * (1/(sk[z1] + 1e-12*Z[z1])) : 0
// before tf32 rounding — the fused "causal adjacency" normalization.
//
// Split-K: gridDim.z = NB * S; s = z / NB, partial C at s*sStride.
// Batch zb = z % NB: offset = (zb/zdiv)*S1 + (zb%zdiv)*S2.
// M % 128 == 0, N % 64 == 0, K % 16 == 0, K >= 32.
// ---------------------------------------------------------------------------
template <int MODE, int TRANSA>
__global__ void __launch_bounds__(256, 2) mma_gemm_k(
    const float* __restrict__ A, const float* __restrict__ Bm,
    float* __restrict__ C,
    int K, int lda, int ldb, int ldc, int zdiv, int S,
    long aS1, long aS2, long bS1, long bS2, long cS1, long cS2,
    long sStride,
    const float* __restrict__ tthr, const float* __restrict__ tsk,
    const float* __restrict__ tz)
{
    __shared__ float sA[2][2048];   // 8KB per stage
    __shared__ float sB[2][1024];   // 4KB per stage

    int NB = gridDim.z / S;
    int s  = blockIdx.z / NB;
    int zb = blockIdx.z % NB;
    int z1 = zb / zdiv, z2 = zb - z1 * zdiv;
    A  += z1 * aS1 + z2 * aS2;
    Bm += z1 * bS1 + z2 * bS2;
    C  += z1 * cS1 + z2 * cS2;
    // split-K offsets
    A += (long)s * K;                       // A is [M, K_total] row-major
    if (MODE == 0) Bm += (long)s * K;       // B is [N, K_total]
    else           Bm += (long)s * K * ldb; // B is [K_total, N]
    C += (long)s * sStride;

    float thrv = 0.f, invv = 0.f;
    if (TRANSA) {
        thrv = tthr[z1];
        invv = 1.0f / (tsk[z1] + 1e-12f * tz[z1]);
    }

    int m0 = blockIdx.y * 128;
    int n0 = blockIdx.x * 64;
    int tid  = threadIdx.x;
    int lane = tid & 31;
    int wid  = tid >> 5;
    int g   = lane >> 2, tig = lane & 3;
    int wm = (wid >> 1) * 32, wn = (wid & 1) * 32;

    // ---- loader coordinates ----
    int arow = tid >> 2;
    int acol = (tid & 3) * 4;
    const float* Ap0 = A + (long)(m0 + arow) * lda + acol;
    const float* Ap1 = Ap0 + (long)64 * lda;
    int kb_a  = acol >> 3;
    int shi_a = (acol >> 2) & 1;
    int aBase0, aBase1;
    {
        int m_l = arow;
        aBase0 = ((m_l >> 4) * 2 + kb_a) * 128 + (m_l & 7) * 4 + shi_a * 2 + ((m_l >> 3) & 1);
        m_l = arow + 64;
        aBase1 = ((m_l >> 4) * 2 + kb_a) * 128 + (m_l & 7) * 4 + shi_a * 2 + ((m_l >> 3) & 1);
    }

    const float* Bp;
    int bAddr[4];
    if (MODE == 0) {
        int brow = tid >> 2;            // n_local
        int bcol = (tid & 3) * 4;       // k offset
        Bp = Bm + (long)(n0 + brow) * ldb + bcol;
        int Nb = brow >> 3, gB = brow & 7;
        int gx = gB ^ (Nb & 7);
        int kb_b = bcol >> 3, shi_b = (bcol >> 2) & 1;
        #pragma unroll
        for (int t = 0; t < 4; t++)
            bAddr[t] = (Nb * 2 + kb_b) * 64 + (t * 8 + gx) * 2 + shi_b;
    } else {
        int krow = tid >> 4;            // k_local (0..15)
        int bn   = (tid & 15) * 4;      // n offset
        Bp = Bm + (long)krow * ldb + n0 + bn;
        int kb_b = krow >> 3, tig_b = krow & 3, shi_b = (krow >> 2) & 1;
        #pragma unroll
        for (int t = 0; t < 4; t++) {
            int n_l = bn + t;
            int Nb = n_l >> 3, gB = n_l & 7;
            int gx = gB ^ (Nb & 7);
            bAddr[t] = (Nb * 2 + kb_b) * 64 + (tig_b * 8 + gx) * 2 + shi_b;
        }
    }

    // ---- consumer fragment addresses ----
    int aIdx0 = ((wm >> 4) * 2) * 128 + (tig * 8 + g) * 4;
    int aIdx1 = ((wm >> 4) * 2 + 2) * 128 + (tig * 8 + g) * 4;
    int bIdx[4];
    #pragma unroll
    for (int nt = 0; nt < 4; nt++) {
        int Nb = (wn >> 3) + nt;
        bIdx[nt] = (Nb * 2) * 64 + (tig * 8 + (g ^ (Nb & 7))) * 2;
    }

    float c[2][4][4] = {};

    float4 ra0, ra1, rb;     // tile being stored to smem
    float4 na0, na1, nb;     // tile in flight (one ahead)

    auto sts = [&](int st) {
        float* SA = sA[st];
        float* SB = sB[st];
        const float* v0 = (const float*)&ra0;
        const float* v1 = (const float*)&ra1;
        const float* vb = (const float*)&rb;
        #pragma unroll
        for (int t = 0; t < 4; t++) {
            float x0 = v0[t], x1 = v1[t];
            if (TRANSA) {
                x0 = (x0 >= thrv) ? x0 * invv : 0.f;
                x1 = (x1 >= thrv) ? x1 * invv : 0.f;
            }
            SA[aBase0 + t * 32] = t32(x0);
            SA[aBase1 + t * 32] = t32(x1);
            SB[bAddr[t]]        = t32(vb[t]);
        }
    };

    auto compute = [&](int p) {
        const float* SA = sA[p];
        const float* SB = sB[p];
        #pragma unroll
        for (int kb = 0; kb < 2; kb++) {
            float4 av0 = *(const float4*)(SA + aIdx0 + kb * 128);
            float4 av1 = *(const float4*)(SA + aIdx1 + kb * 128);
            float2 bv[4];
            #pragma unroll
            for (int nt = 0; nt < 4; nt++)
                bv[nt] = *(const float2*)(SB + bIdx[nt] + kb * 64);
            float a0[4] = {av0.x, av0.y, av0.z, av0.w};
            float a1[4] = {av1.x, av1.y, av1.z, av1.w};
            #pragma unroll
            for (int nt = 0; nt < 4; nt++) {
                float bb[2] = {bv[nt].x, bv[nt].y};
                mma_tf32(c[0][nt], a0, bb);
                mma_tf32(c[1][nt], a1, bb);
            }
        }
    };

    // prologue: load k=0 and k=16
    ra0 = *(const float4*)Ap0;
    ra1 = *(const float4*)Ap1;
    rb  = *(const float4*)Bp;
    Ap0 += 16; Ap1 += 16;
    if (MODE == 0) Bp += 16; else Bp += (long)16 * ldb;
    na0 = *(const float4*)Ap0;
    na1 = *(const float4*)Ap1;
    nb  = *(const float4*)Bp;
    sts(0);
    __syncthreads();

    int p = 0;
    for (int k0 = 32; k0 < K; k0 += 16) {
        Ap0 += 16; Ap1 += 16;
        if (MODE == 0) Bp += 16; else Bp += (long)16 * ldb;
        ra0 = na0; ra1 = na1; rb = nb;      // shift: k0-16 -> store set
        na0 = *(const float4*)Ap0;          // issue LDG for tile k0
        na1 = *(const float4*)Ap1;
        nb  = *(const float4*)Bp;
        compute(p);                          // consume tile k0-32
        sts(p ^ 1);                          // store tile k0-16
        __syncthreads();
        p ^= 1;
    }
    // tail: two stages remain (last loaded tile still in na)
    ra0 = na0; ra1 = na1; rb = nb;
    compute(p);
    sts(p ^ 1);
    __syncthreads();
    compute(p ^ 1);

    // epilogue (no bias — applied by the split-K reducer)
    #pragma unroll
    for (int mt = 0; mt < 2; mt++) {
        #pragma unroll
        for (int nt = 0; nt < 4; nt++) {
            int m = m0 + wm + mt * 16 + g;
            int n = n0 + wn + nt * 8 + 2 * tig;
            *(float2*)&C[(long)m * ldc + n] =
                make_float2(c[mt][nt][0], c[mt][nt][1]);
            *(float2*)&C[(long)(m + 8) * ldc + n] =
                make_float2(c[mt][nt][2], c[mt][nt][3]);
        }
    }
}

// ---------------------------------------------------------------------------
// Split-K reducer: out[i] = sum_s part[i + s*sStride] (+ bias[col]).
// All counts in float4 units; ldc % 4 == 0.
// ---------------------------------------------------------------------------
__global__ void __launch_bounds__(256) reduce_k(
    const float* __restrict__ part, float* __restrict__ outp,
    const float* __restrict__ bias, int ldc,
    long n4, int S, long sStride4)
{
    const float4* p4 = reinterpret_cast<const float4*>(part);
    float4* o4 = reinterpret_cast<float4*>(outp);
    for (long i = blockIdx.x * 256 + threadIdx.x; i < n4;
         i += (long)gridDim.x * 256) {
        float4 a = p4[i];
        for (int s = 1; s < S; s++) {
            float4 b = p4[i + s * sStride4];
            a.x += b.x; a.y += b.y; a.z += b.z; a.w += b.w;
        }
        if (bias) {
            int col = (int)((i * 4) % ldc);
            a.x += bias[col]; a.y += bias[col + 1];
            a.z += bias[col + 2]; a.w += bias[col + 3];
        }
        o4[i] = a;
    }
}

// ---------------------------------------------------------------------------
// Attention scores: s_i/s_j per (b,h,n) — one warp per row, float4 loads.
// ---------------------------------------------------------------------------
__global__ void attn_scores_k(const float* __restrict__ hp,
                              const float* __restrict__ attn,
                              float* __restrict__ si, float* __restrict__ sj)
{
    int w = (blockIdx.x * blockDim.x + threadIdx.x) >> 5;
    int lane = threadIdx.x & 31;
    if (w >= B_ * NH * NV) return;
    int b = w / (NH * NV);
    int rem = w - b * NH * NV;
    int h = rem / NV;
    int n = rem - h * NV;

    const float4* v4  = (const float4*)(hp + ((long)(b * NV + n)) * FD + h * DHD);
    const float4* ai4 = (const float4*)(attn + h * 2 * DHD);
    const float4* aj4 = ai4 + DHD / 4;
    float s1 = 0.f, s2 = 0.f;
    #pragma unroll
    for (int q = 0; q < 2; q++) {
        int idx = lane + 32 * q;
        float4 xv = v4[idx];
        float4 av = ai4[idx];
        float4 bv = aj4[idx];
        s1 = fmaf(xv.x, av.x, fmaf(xv.y, av.y, fmaf(xv.z, av.z, fmaf(xv.w, av.w, s1))));
        s2 = fmaf(xv.x, bv.x, fmaf(xv.y, bv.y, fmaf(xv.z, bv.z, fmaf(xv.w, bv.w, s2))));
    }
    s1 = warpSum(s1);
    s2 = warpSum(s2);
    if (lane == 0) { si[w] = s1; sj[w] = s2; }
}

// ---------------------------------------------------------------------------
// Attention softmax per (b,h,i) row: alpha = softmax_j(lrelu(s_i + s_j)).
// ---------------------------------------------------------------------------
__global__ void __launch_bounds__(128) attn_softmax_k(
    const float* __restrict__ si, const float* __restrict__ sj,
    float* __restrict__ alpha)
{
    int row = blockIdx.x;                 // [0, B*NH*NV)
    int bh  = row / NV;
    float s_i = si[row];
    const float* sjr = sj + (long)bh * NV;
    __shared__ float red[4];

    int t = threadIdx.x;
    float loc[4];
    float m = -3.4e38f;
    #pragma unroll
    for (int r = 0; r < 4; r++) {
        float e = s_i + sjr[t + 128 * r];
        e = (e >= 0.f) ? e : 0.2f * e;
        loc[r] = e;
        m = fmaxf(m, e);
    }
    m = warpMax(m);
    if ((t & 31) == 0) red[t >> 5] = m;
    __syncthreads();
    float bm = fmaxf(fmaxf(red[0], red[1]), fmaxf(red[2], red[3]));

    float s = 0.f;
    #pragma unroll
    for (int r = 0; r < 4; r++) {
        float ex = expf(loc[r] - bm);
        loc[r] = ex;
        s += ex;
    }
    s = warpSum(s);
    __syncthreads();
    if ((t & 31) == 0) red[t >> 5] = s;
    __syncthreads();
    float inv = 1.0f / (red[0] + red[1] + red[2] + red[3]);
    #pragma unroll
    for (int r = 0; r < 4; r++)
        alpha[(long)row * NV + t + 128 * r] = loc[r] * inv;
}

// ---------------------------------------------------------------------------
// Fused edge scorer + global max (feeds softmax):
// edge[b,i,j] = b2 + sum_a relu(pi[b,i,a]+pj[b,j,a]) * w2[a]
// ---------------------------------------------------------------------------
__global__ void __launch_bounds__(256) edge_k(
    const float* __restrict__ pi, const float* __restrict__ pj,
    const float* __restrict__ w2, const float* __restrict__ b2,
    float* __restrict__ edge, unsigned* __restrict__ maxb)
{
    int b  = blockIdx.z;
    int i0 = blockIdx.y * 32, j0 = blockIdx.x * 32;
    __shared__ float spi[32][33];
    __shared__ float spj[32][33];
    __shared__ float sw2[32];

    const float* PI = pi + (long)b * NV * AHD;
    const float* PJ = pj + (long)b * NV * AHD;
    int tid = threadIdx.x;
    int tx = tid & 31, ty = tid >> 5;   // ty 0..7
    float acc[4] = {0.f, 0.f, 0.f, 0.f};

    for (int a0 = 0; a0 < AHD; a0 += 32) {
        #pragma unroll
        for (int r = 0; r < 4; r++) {
            spi[ty + 8 * r][tx] = PI[(long)(i0 + ty + 8 * r) * AHD + a0 + tx];
            spj[ty + 8 * r][tx] = PJ[(long)(j0 + ty + 8 * r) * AHD + a0 + tx];
        }
        if (tid < 32) sw2[tid] = w2[a0 + tid];
        __syncthreads();

        #pragma unroll
        for (int a = 0; a < 32; a++) {
            float pjv = spj[tx][a];
            float wv  = sw2[a];
            #pragma unroll
            for (int r = 0; r < 4; r++) {
                float v = spi[ty + 8 * r][a] + pjv;
                acc[r] = fmaf(fmaxf(v, 0.f), wv, acc[r]);
            }
        }
        __syncthreads();
    }
    float bb = b2[0];
    float lm = -3.4e38f;
    #pragma unroll
    for (int r = 0; r < 4; r++) {
        float v = acc[r] + bb;
        edge[((long)b * NV + i0 + ty + 8 * r) * NV + j0 + tx] = v;
        lm = fmaxf(lm, v);
    }
    lm = warpMax(lm);
    __shared__ float red[8];
    if (tx == 0) red[ty] = lm;
    __syncthreads();
    if (tid == 0) {
        float bm = red[0];
        #pragma unroll
        for (int i = 1; i < 8; i++) bm = fmaxf(bm, red[i]);
        atomicMax(maxb + b, fenc(bm));
    }
}

// ---------------------------------------------------------------------------
// Softmax + top-k selection pipeline over the flat (B, N*N) edge scores.
// ---------------------------------------------------------------------------
__global__ void init_k(unsigned* maxb, float* Z, float* sk,
                       unsigned* pfx, int* rnk, int* hist)
{
    int t = blockIdx.x * blockDim.x + threadIdx.x;
    if (t < B_) { maxb[t] = 0u; Z[t] = 0.f; sk[t] = 0.f; pfx[t] = 0u; rnk[t] = RANK_; }
    for (int i = t; i < B_ * 4 * 256; i += gridDim.x * blockDim.x) hist[i] = 0;
}

// exp + Z sum + radix pass-0 histogram (top byte), fused.
__global__ void __launch_bounds__(256) exp_k(const float* __restrict__ edge,
                                             const unsigned* __restrict__ maxb,
                                             float* __restrict__ expb,
                                             float* __restrict__ Z,
                                             int* __restrict__ hist)
{
    int b = blockIdx.y;
    float emax = fdec(maxb[b]);
    const float* e = edge + (long)b * NSQ;
    float* o = expb + (long)b * NSQ;
    __shared__ int sh[256];
    sh[threadIdx.x] = 0;
    __syncthreads();
    float s = 0.f;
    for (int i = blockIdx.x * 256 + threadIdx.x; i < NSQ; i += 64 * 256) {
        float ex = expf((e[i] - emax) * INV_TEMP);
        o[i] = ex;
        s += ex;
        atomicAdd(&sh[__float_as_uint(ex) >> 24], 1);
    }
    s = warpSum(s);
    __shared__ float red[8];
    if ((threadIdx.x & 31) == 0) red[threadIdx.x >> 5] = s;
    __syncthreads();
    if (threadIdx.x == 0) {
        float t = 0.f;
        #pragma unroll
        for (int i = 0; i < 8; i++) t += red[i];
        atomicAdd(Z + b, t);
    }
    int c = sh[threadIdx.x];
    if (c) atomicAdd(&hist[(long)b * 4 * 256 + threadIdx.x], c);
}

// Byte-radix histogram over positive-float bit patterns (passes 1..3).
__global__ void __launch_bounds__(256) hist_k(const float* __restrict__ expb,
                                              const unsigned* __restrict__ pfx_,
                                              int* __restrict__ hist, int pass)
{
    int b = blockIdx.y;
    const unsigned* u = reinterpret_cast<const unsigned*>(expb + (long)b * NSQ);
    unsigned pfx = pfx_[b];
    int shift = 24 - 8 * pass;
    __shared__ int sh[256];
    sh[threadIdx.x] = 0;
    __syncthreads();
    for (int i = blockIdx.x * 256 + threadIdx.x; i < NSQ; i += 64 * 256) {
        unsigned v = u[i];
        if ((v >> (shift + 8)) == pfx)
            atomicAdd(&sh[(v >> shift) & 255], 1);
    }
    __syncthreads();
    int c = sh[threadIdx.x];
    if (c) atomicAdd(&hist[((long)b * 4 + pass) * 256 + threadIdx.x], c);
}

__global__ void decide_k(const int* __restrict__ hist, unsigned* pfx, int* rnk,
                         float* thr, int pass)
{
    if (threadIdx.x != 0) return;
    int b = blockIdx.x;
    const int* H = hist + ((long)b * 4 + pass) * 256;
    int rk = rnk[b];
    unsigned p = pfx[b];
    int cum = 0, bkt = 255;
    for (int t = 0; t < 256; t++) {
        int c = H[t];
        if (cum + c > rk) { bkt = t; break; }
        cum += c;
    }
    p = (p << 8) | (unsigned)bkt;
    pfx[b] = p;
    rnk[b] = rk - cum;
    if (pass == 3) thr[b] = __uint_as_float(p);
}

__global__ void __launch_bounds__(256) skept_k(const float* __restrict__ expb,
                                               const float* __restrict__ thr,
                                               float* __restrict__ sk)
{
    int b = blockIdx.y;
    float t = thr[b];
    const float* e = expb + (long)b * NSQ;
    float s = 0.f;
    for (int i = blockIdx.x * 256 + threadIdx.x; i < NSQ; i += 64 * 256) {
        float v = e[i];
        if (v >= t) s += v;
    }
    s = warpSum(s);
    __shared__ float red[8];
    if ((threadIdx.x & 31) == 0) red[threadIdx.x >> 5] = s;
    __syncthreads();
    if (threadIdx.x == 0) {
        float bs = 0.f;
        #pragma unroll
        for (int i = 0; i < 8; i++) bs += red[i];
        atomicAdd(sk + b, bs);
    }
}

// ---------------------------------------------------------------------------
// Fused batchnorm (+relu), stats over all R = B*N rows jointly.
// ---------------------------------------------------------------------------
__global__ void __launch_bounds__(256) bn_relu_k(float* __restrict__ h,
                                                 const float* __restrict__ gam,
                                                 const float* __restrict__ bet,
                                                 int R, int C)
{
    int l = threadIdx.x & 63;
    int part = threadIdx.x >> 6;
    int c = blockIdx.x * 64 + l;
    float s = 0.f, s2 = 0.f;
    for (int r = part; r < R; r += 4) {
        float v = h[(long)r * C + c];
        s += v;
        s2 = fmaf(v, v, s2);
    }
    __shared__ float sh1[4][64], sh2[4][64], sm[64], sv[64];
    sh1[part][l] = s;
    sh2[part][l] = s2;
    __syncthreads();
    if (part == 0) {
        float t1 = sh1[0][l] + sh1[1][l] + sh1[2][l] + sh1[3][l];
        float t2 = sh2[0][l] + sh2[1][l] + sh2[2][l] + sh2[3][l];
        float mean = t1 / (float)R;
        float var  = t2 / (float)R - mean * mean;
        sm[l] = mean;
        sv[l] = rsqrtf(var + 1e-5f);
    }
    __syncthreads();
    float scale = sv[l] * gam[c];
    float shift = bet[c] - sm[l] * scale;
    for (int r = part; r < R; r += 4) {
        long idx = (long)r * C + c;
        h[idx] = fmaxf(fmaf(h[idx], scale, shift), 0.f);
    }
}

// ---------------------------------------------------------------------------
// Final: feat = mean_n h4[b,n,:]; out = feat @ cls_w^T + cls_b
// ---------------------------------------------------------------------------
__global__ void __launch_bounds__(128) final_k(const float* __restrict__ h4,
                                               const float* __restrict__ cw,
                                               const float* __restrict__ cb,
                                               float* __restrict__ out)
{
    int b = blockIdx.x;
    int c = threadIdx.x;   // 128 = OD
    __shared__ float sf[OD];
    float s = 0.f;
    for (int n = 0; n < NV; n++)
        s += h4[((long)b * NV + n) * OD + c];
    sf[c] = s * (1.0f / (float)NV);
    __syncthreads();
    if (c < NC) {
        float d = cb[c];
        for (int f = 0; f < OD; f++)
            d = fmaf(sf[f], cw[c * OD + f], d);
        out[b * NC + c] = d;
    }
}

// ---------------------------------------------------------------------------
// Launcher
// ---------------------------------------------------------------------------
extern "C" void kernel_launch(void* const* d_in, const int* in_sizes, int n_in,
                              void* d_out, int out_size)
{
    const float* x    = (const float*)d_in[0];
    const float* Wg   = (const float*)d_in[1];
    const float* attn = (const float*)d_in[2];
    const float* W1   = (const float*)d_in[3];
    const float* b1   = (const float*)d_in[4];
    const float* w2   = (const float*)d_in[5];
    const float* b2   = (const float*)d_in[6];
    const float* gc1w = (const float*)d_in[7];
    const float* gc1b = (const float*)d_in[8];
    const float* bn1g = (const float*)d_in[9];
    const float* bn1b = (const float*)d_in[10];
    const float* gc2w = (const float*)d_in[11];
    const float* gc2b = (const float*)d_in[12];
    const float* bn2g = (const float*)d_in[13];
    const float* bn2b = (const float*)d_in[14];
    const float* clsw = (const float*)d_in[15];
    const float* clsb = (const float*)d_in[16];
    float* out = (float*)d_out;

    float* sb = nullptr;
    cudaGetSymbolAddress((void**)&sb, g_s);

    float* HP = sb + O_HP;
    float* SI = sb + O_SI;
    float* SJ = sb + O_SJ;
    float* AL = sb + O_AL;
    float* NF = sb + O_NF;
    float* PI = sb + O_PI;
    float* PJ = sb + O_PJ;
    float* ED = sb + O_ED;
    float* EX = sb + O_EX;
    float* H1 = sb + O_H1;
    float* H2 = sb + O_H2;
    float* H3 = sb + O_H3;
    float* H4 = sb + O_H4;
    float* PART = sb + O_PART;
    unsigned* MAXB = reinterpret_cast<unsigned*>(sb + O_MAXB);
    float* Zp  = sb + O_Z;
    float* SK  = sb + O_SK;
    float* THR = sb + O_THR;
    unsigned* PFX = reinterpret_cast<unsigned*>(sb + O_PFX);
    int* RNK = reinterpret_cast<int*>(sb + O_RNK);
    int* HIST = reinterpret_cast<int*>(sb + O_HIST);

    const int RG = 256;   // reduce grid
    const float* NP = nullptr;

    // 0. init selection state (MAXB must be ready before edge_k)
    init_k<<<8, 256>>>(MAXB, Zp, SK, PFX, RNK, HIST);

    // 1. hp = x @ Wg^T : M=1024, N=1024, K=1024, S=2 -> 256 CTAs
    mma_gemm_k<0, 0><<<dim3(FD / 64, (B_ * NV) / 128, 2), 256>>>(
        x, Wg, PART, 512, FD, FD, FD, 1, 2, 0, 0, 0, 0, 0, 0, 1048576,
        NP, NP, NP);
    reduce_k<<<RG, 256>>>(PART, HP, nullptr, FD, 262144, 2, 262144);

    // 2. s_i, s_j
    attn_scores_k<<<(B_ * NH * NV * 32 + 255) / 256, 256>>>(HP, attn, SI, SJ);

    // 3. alpha = softmax(lrelu(s_i + s_j))
    attn_softmax_k<<<B_ * NH * NV, 128>>>(SI, SJ, AL);

    // 4. node_feats = alpha @ hp_heads  (NB=8 over b,h; S=2 -> 256 CTAs)
    mma_gemm_k<1, 0><<<dim3(DHD / 64, NV / 128, 8 * 2), 256>>>(
        AL, HP, PART, 256, NV, FD, FD, NH, 2,
        (long)NH * NSQ, (long)NSQ, (long)NV * FD, (long)DHD,
        (long)NV * FD, (long)DHD, 1048576, NP, NP, NP);
    reduce_k<<<RG, 256>>>(PART, NF, nullptr, FD, 262144, 2, 262144);

    // 5+6. pi|pj = nf @ W1{i,j}^T  (NB=2 halves, S=4 -> 256 CTAs);
    // reducer adds b1 to both halves (b1 is zeros in this problem instance).
    mma_gemm_k<0, 0><<<dim3(AHD / 64, (B_ * NV) / 128, 2 * 4), 256>>>(
        NF, W1, PART, 256, FD, 2 * FD, AHD, 2, 4,
        0, 0, 0, (long)FD, 0, (long)B_ * NV * AHD, 524288, NP, NP, NP);
    reduce_k<<<RG, 256>>>(PART, PI, b1, AHD, 131072, 4, 131072);

    // 7. edge scores (fused relu-dot with w2) + global max
    edge_k<<<dim3(NV / 32, NV / 32, B_), 256>>>(PI, PJ, w2, b2, ED, MAXB);

    // 8-17. softmax + rank-52429 threshold; adj transform fused into GEMMs.
    exp_k<<<dim3(64, B_), 256>>>(ED, MAXB, EX, Zp, HIST);
    decide_k<<<B_, 32>>>(HIST, PFX, RNK, THR, 0);
    for (int pass = 1; pass < 4; pass++) {
        hist_k<<<dim3(64, B_), 256>>>(EX, PFX, HIST, pass);
        decide_k<<<B_, 32>>>(HIST, PFX, RNK, THR, pass);
    }
    skept_k<<<dim3(64, B_), 256>>>(EX, THR, SK);

    // 18. h1 = adj(EX) @ nf   (NB=2 batches, S=2 -> 256 CTAs; TRANSA)
    mma_gemm_k<1, 1><<<dim3(FD / 64, NV / 128, 2 * 2), 256>>>(
        EX, NF, PART, 256, NV, FD, FD, 1, 2,
        (long)NSQ, 0, (long)NV * FD, 0, (long)NV * FD, 0, 1048576,
        THR, SK, Zp);
    reduce_k<<<RG, 256>>>(PART, H1, nullptr, FD, 262144, 2, 262144);

    // 19. h2 = h1 @ gc1_w^T + gc1_b  (S=4 -> 256 CTAs)
    mma_gemm_k<0, 0><<<dim3(HIDD / 64, (B_ * NV) / 128, 4), 256>>>(
        H1, gc1w, PART, 256, FD, FD, HIDD, 1, 4, 0, 0, 0, 0, 0, 0, 524288,
        NP, NP, NP);
    reduce_k<<<RG, 256>>>(PART, H2, gc1b, HIDD, 131072, 4, 131072);

    // 20. bn1 + relu
    bn_relu_k<<<HIDD / 64, 256>>>(H2, bn1g, bn1b, B_ * NV, HIDD);

    // 21. h3 = adj(EX) @ h2  (NB=2, S=4 -> 256 CTAs; TRANSA)
    mma_gemm_k<1, 1><<<dim3(HIDD / 64, NV / 128, 2 * 4), 256>>>(
        EX, H2, PART, 128, NV, HIDD, HIDD, 1, 4,
        (long)NSQ, 0, (long)NV * HIDD, 0, (long)NV * HIDD, 0, 524288,
        THR, SK, Zp);
    reduce_k<<<RG, 256>>>(PART, H3, nullptr, HIDD, 131072, 4, 131072);

    // 22. h4 = h3 @ gc2_w^T + gc2_b  (S=8 -> 128 CTAs)
    mma_gemm_k<0, 0><<<dim3(OD / 64, (B_ * NV) / 128, 8), 256>>>(
        H3, gc2w, PART, 64, HIDD, HIDD, OD, 1, 8, 0, 0, 0, 0, 0, 0, 131072,
        NP, NP, NP);
    reduce_k<<<RG, 256>>>(PART, H4, gc2b, OD, 32768, 8, 32768);

    // 23. bn2 + relu
    bn_relu_k<<<OD / 64, 256>>>(H4, bn2g, bn2b, B_ * NV, OD);

    // 24. mean-pool + classifier
    final_k<<<B_, 128>>>(H4, clsw, clsb, out);
}